// round 3
// baseline (speedup 1.0000x reference)
#include <cuda_runtime.h>
#include <math.h>
#include <stdint.h>
#include <stddef.h>

#define BB 64
#define WW 64
#define NN 8192
#define MODES 16
#define J2 32
#define NT 128
#define TBC (NN / NT)
#define SSTR 132

__device__ float g_hA[(size_t)BB * WW * NN];
__device__ float g_hB[(size_t)BB * WW * NN];
__device__ float g_basis[(size_t)J2 * NN];            // [j][n]
__device__ float g_pF[(size_t)BB * TBC * J2 * WW];    // partial fwd DFT [b][chunk][j][c]
__device__ float g_F[(size_t)BB * J2 * WW];           // [b][j][c]
__device__ float g_Gp[(size_t)BB * WW * J2];          // [b][o][j] synth coefs

__global__ void basis_kernel() {
    int n = blockIdx.x * 256 + threadIdx.x;
    if (n >= NN) return;
#pragma unroll
    for (int m = 0; m < MODES; m++) {
        int r = (m * n) & (NN - 1);
        float tf = 2.0f * (float)r / (float)NN;
        float s, c;
        sincospif(tf, &s, &c);
        g_basis[(size_t)(2 * m) * NN + n] = c;
        g_basis[(size_t)(2 * m + 1) * NN + n] = s;
    }
}

__device__ __forceinline__ float gelu_exact(float v) {
    return 0.5f * v * (1.0f + erff(v * 0.70710678118654752f));
}

// dir==0: read g_hA write g_hB ; dir==1: read g_hB write g_hA
template <bool FIRST, bool GELU, bool DFT>
__global__ __launch_bounds__(256, 2)
void combine_kernel(int dir,
                    const float* __restrict__ cw_l, const float* __restrict__ cb_l,
                    const float* __restrict__ xg,  const float* __restrict__ tg,
                    const float* __restrict__ fc0w, const float* __restrict__ fc0b)
{
    extern __shared__ float sm[];
    float* hs  = sm;                    // 64*SSTR
    float* bas = hs  + 64 * SSTR;       // 32*128
    float* cwT = bas + J2 * NT;         // 64*65
    float* gps = cwT + 64 * 65;         // 64*33
    float* cbs = gps + 64 * 33;         // 64
    float* xs  = cbs + 64;              // 128
    float* ts  = xs  + NT;              // 128
    float* w0s = ts  + NT;              // 128

    const int tid = threadIdx.x;
    const int b   = blockIdx.y;
    const int n0  = blockIdx.x * NT;

    const float* __restrict__ h_in  = dir ? g_hB : g_hA;
    float* __restrict__       h_out = dir ? g_hA : g_hB;

    if (!FIRST) {
        for (int i = tid; i < 64 * NT; i += 256) {
            int c = i >> 7, n = i & (NT - 1);
            hs[c * SSTR + n] = h_in[((size_t)(b * 64 + c)) * NN + n0 + n];
        }
        for (int i = tid; i < 4096; i += 256) {
            int o = i >> 6, c = i & 63;
            cwT[c * 65 + o] = cw_l[o * 64 + c];
        }
        for (int i = tid; i < 2048; i += 256) {
            int o = i >> 5, j = i & 31;
            gps[o * 33 + j] = g_Gp[(size_t)(b * 64 + o) * 32 + j];
        }
        if (tid < 64) cbs[tid] = cb_l[tid];
    } else {
        for (int i = tid; i < NT; i += 256) {
            xs[i] = xg[(size_t)b * NN + n0 + i];
            ts[i] = tg[(size_t)b * NN + n0 + i];
        }
        if (tid < 128) w0s[tid] = fc0w[tid];
        if (tid < 64)  cbs[tid] = fc0b[tid];
    }
    for (int i = tid; i < J2 * NT; i += 256) {
        int j = i >> 7, n = i & (NT - 1);
        bas[j * NT + n] = g_basis[(size_t)j * NN + n0 + n];
    }
    __syncthreads();

    // phase 1: 8 o-rows x 4 n-cols per thread
    const int tx = tid & 7;
    const int ty = tid >> 3;
    float acc[8][4];

    if (FIRST) {
#pragma unroll
        for (int oo = 0; oo < 8; oo++) {
            int o = tx * 8 + oo;
            float wa = w0s[o], wb = w0s[64 + o], bv = cbs[o];
#pragma unroll
            for (int ni = 0; ni < 4; ni++)
                acc[oo][ni] = fmaf(wa, xs[ty * 4 + ni], fmaf(wb, ts[ty * 4 + ni], bv));
        }
    } else {
#pragma unroll
        for (int oo = 0; oo < 8; oo++) {
            float bv = cbs[tx * 8 + oo];
#pragma unroll
            for (int ni = 0; ni < 4; ni++) acc[oo][ni] = bv;
        }
#pragma unroll 4
        for (int c = 0; c < 64; c++) {
            float4 hv = *(const float4*)&hs[c * SSTR + ty * 4];
#pragma unroll
            for (int oo = 0; oo < 8; oo++) {
                float wv = cwT[c * 65 + tx * 8 + oo];
                acc[oo][0] = fmaf(wv, hv.x, acc[oo][0]);
                acc[oo][1] = fmaf(wv, hv.y, acc[oo][1]);
                acc[oo][2] = fmaf(wv, hv.z, acc[oo][2]);
                acc[oo][3] = fmaf(wv, hv.w, acc[oo][3]);
            }
        }
#pragma unroll 4
        for (int j = 0; j < 32; j++) {
            float4 bv4 = *(const float4*)&bas[j * NT + ty * 4];
#pragma unroll
            for (int oo = 0; oo < 8; oo++) {
                float g = gps[(tx * 8 + oo) * 33 + j];
                acc[oo][0] = fmaf(g, bv4.x, acc[oo][0]);
                acc[oo][1] = fmaf(g, bv4.y, acc[oo][1]);
                acc[oo][2] = fmaf(g, bv4.z, acc[oo][2]);
                acc[oo][3] = fmaf(g, bv4.w, acc[oo][3]);
            }
        }
    }

    if (GELU) {
#pragma unroll
        for (int oo = 0; oo < 8; oo++)
#pragma unroll
            for (int ni = 0; ni < 4; ni++) acc[oo][ni] = gelu_exact(acc[oo][ni]);
    }

#pragma unroll
    for (int oo = 0; oo < 8; oo++) {
        int o = tx * 8 + oo;
        float4 v = make_float4(acc[oo][0], acc[oo][1], acc[oo][2], acc[oo][3]);
        *(float4*)&h_out[((size_t)(b * 64 + o)) * NN + n0 + ty * 4] = v;
    }

    if (DFT) {
        // reuse hs for the just-produced tile
        __syncthreads();
#pragma unroll
        for (int oo = 0; oo < 8; oo++) {
            int o = tx * 8 + oo;
#pragma unroll
            for (int ni = 0; ni < 4; ni++) hs[o * SSTR + ty * 4 + ni] = acc[oo][ni];
        }
        __syncthreads();

        // phase 2: forward-DFT partials. c = channel, 8 j per thread.
        const int c  = tid & 63;
        const int jg = tid >> 6;
        float facc[8];
#pragma unroll
        for (int jj = 0; jj < 8; jj++) facc[jj] = 0.0f;

        for (int nb = 0; nb < NT / 8; nb++) {
            float hb[8];
#pragma unroll
            for (int k = 0; k < 8; k++) hb[k] = hs[c * SSTR + nb * 8 + k];
#pragma unroll
            for (int jj = 0; jj < 8; jj++) {
                int j = jg * 8 + jj;
                const float* bp = &bas[j * NT + nb * 8];
                float s = facc[jj];
#pragma unroll
                for (int k = 0; k < 8; k++) s = fmaf(hb[k], bp[k], s);
                facc[jj] = s;
            }
        }
        size_t base = ((size_t)b * TBC + blockIdx.x) * J2;
#pragma unroll
        for (int jj = 0; jj < 8; jj++)
            g_pF[(base + jg * 8 + jj) * WW + c] = facc[jj];
    }
}

__global__ void reduce_kernel() {
    int b = blockIdx.x;
    for (int idx = threadIdx.x; idx < J2 * WW; idx += 256) {
        float s = 0.0f;
        for (int ch = 0; ch < TBC; ch++)
            s += g_pF[((size_t)b * TBC + ch) * (J2 * WW) + idx];
        g_F[(size_t)b * (J2 * WW) + idx] = s;
    }
}

// G = (Fr - i Fs)(wr + i wi); Gp[2m]=c_m ReG, Gp[2m+1]=-c_m ImG; c_0=1/N else 2/N
__global__ void modemix_kernel(const float* __restrict__ swr,
                               const float* __restrict__ swi) {
    __shared__ float fs[64 * 33];   // [c][j]
    int b = blockIdx.x, tid = threadIdx.x;
    for (int i = tid; i < 2048; i += 256) {
        int j = i >> 6, c = i & 63;
        fs[c * 33 + j] = g_F[(size_t)b * 2048 + i];
    }
    __syncthreads();
    int m = tid & 15, og = tid >> 4;
    float re[4] = {0, 0, 0, 0}, im[4] = {0, 0, 0, 0};
    for (int i = 0; i < 64; i++) {
        float fr = fs[i * 33 + 2 * m];
        float fn = fs[i * 33 + 2 * m + 1];
#pragma unroll
        for (int oo = 0; oo < 4; oo++) {
            int o = og * 4 + oo;
            float wr = swr[(i * 64 + o) * 16 + m];
            float wi = swi[(i * 64 + o) * 16 + m];
            re[oo] = fmaf(fr, wr, fmaf(fn, wi, re[oo]));
            im[oo] = fmaf(fr, wi, fmaf(-fn, wr, im[oo]));
        }
    }
    float cm = (m == 0 ? 1.0f : 2.0f) / (float)NN;
#pragma unroll
    for (int oo = 0; oo < 4; oo++) {
        int o = og * 4 + oo;
        g_Gp[(size_t)(b * 64 + o) * 32 + 2 * m]     =  cm * re[oo];
        g_Gp[(size_t)(b * 64 + o) * 32 + 2 * m + 1] = -cm * im[oo];
    }
}

__global__ __launch_bounds__(256, 2)
void fc12_kernel(const float* __restrict__ w1, const float* __restrict__ b1,
                 const float* __restrict__ w2, const float* __restrict__ b2,
                 float* __restrict__ out) {
    extern __shared__ float sm[];
    float* hs  = sm;                  // 64*SSTR
    float* w1s = hs + 64 * SSTR;      // 64*SSTR
    float* w2s = w1s + 64 * SSTR;     // 128
    float* b1s = w2s + 128;           // 128

    int tid = threadIdx.x, b = blockIdx.y, n0 = blockIdx.x * NT;
    const float* __restrict__ h = g_hA;

    for (int i = tid; i < 64 * NT; i += 256) {
        int c = i >> 7, n = i & (NT - 1);
        hs[c * SSTR + n] = h[((size_t)(b * 64 + c)) * NN + n0 + n];
    }
    for (int i = tid; i < 64 * 128; i += 256) {
        int c = i >> 7, j = i & 127;
        w1s[c * SSTR + j] = w1[i];
    }
    if (tid < 128) { w2s[tid] = w2[tid]; b1s[tid] = b1[tid]; }
    __syncthreads();

    int jg = tid & 7;     // j = jj*8 + jg
    int ng = tid >> 3;    // n = ng*4 .. +3

    float hacc[16][4];
#pragma unroll
    for (int jj = 0; jj < 16; jj++) {
        float bv = b1s[jj * 8 + jg];
#pragma unroll
        for (int ni = 0; ni < 4; ni++) hacc[jj][ni] = bv;
    }
#pragma unroll 2
    for (int c = 0; c < 64; c++) {
        float4 hv = *(const float4*)&hs[c * SSTR + ng * 4];
#pragma unroll
        for (int jj = 0; jj < 16; jj++) {
            float wv = w1s[c * SSTR + jj * 8 + jg];
            hacc[jj][0] = fmaf(wv, hv.x, hacc[jj][0]);
            hacc[jj][1] = fmaf(wv, hv.y, hacc[jj][1]);
            hacc[jj][2] = fmaf(wv, hv.z, hacc[jj][2]);
            hacc[jj][3] = fmaf(wv, hv.w, hacc[jj][3]);
        }
    }
    float op[4] = {0, 0, 0, 0};
#pragma unroll
    for (int jj = 0; jj < 16; jj++) {
        float wv = w2s[jj * 8 + jg];
#pragma unroll
        for (int ni = 0; ni < 4; ni++)
            op[ni] = fmaf(wv, gelu_exact(hacc[jj][ni]), op[ni]);
    }
#pragma unroll
    for (int ni = 0; ni < 4; ni++) {
        op[ni] += __shfl_down_sync(0xffffffffu, op[ni], 4, 8);
        op[ni] += __shfl_down_sync(0xffffffffu, op[ni], 2, 8);
        op[ni] += __shfl_down_sync(0xffffffffu, op[ni], 1, 8);
    }
    if (jg == 0) {
        float bv = b2[0];
#pragma unroll
        for (int ni = 0; ni < 4; ni++)
            out[(size_t)b * NN + n0 + ng * 4 + ni] = op[ni] + bv;
    }
}

static const int CMB_SMEM = (64 * SSTR + J2 * NT + 64 * 65 + 64 * 33 + 64 + 3 * 128) * 4;
static const int FC_SMEM  = (64 * SSTR * 2 + 256) * 4;

extern "C" void kernel_launch(void* const* d_in, const int* in_sizes, int n_in,
                              void* d_out, int out_size) {
    const float* x    = (const float*)d_in[0];
    const float* t    = (const float*)d_in[1];
    const float* fc0w = (const float*)d_in[2];
    const float* fc0b = (const float*)d_in[3];
    const float* swr  = (const float*)d_in[4];
    const float* swi  = (const float*)d_in[5];
    const float* cw   = (const float*)d_in[6];
    const float* cb   = (const float*)d_in[7];
    const float* w1   = (const float*)d_in[8];
    const float* b1   = (const float*)d_in[9];
    const float* w2   = (const float*)d_in[10];
    const float* b2   = (const float*)d_in[11];
    float* out = (float*)d_out;

    cudaFuncSetAttribute(combine_kernel<true,  false, true >, cudaFuncAttributeMaxDynamicSharedMemorySize, CMB_SMEM);
    cudaFuncSetAttribute(combine_kernel<false, true,  true >, cudaFuncAttributeMaxDynamicSharedMemorySize, CMB_SMEM);
    cudaFuncSetAttribute(combine_kernel<false, false, false>, cudaFuncAttributeMaxDynamicSharedMemorySize, CMB_SMEM);
    cudaFuncSetAttribute(fc12_kernel, cudaFuncAttributeMaxDynamicSharedMemorySize, FC_SMEM);

    dim3 g(TBC, BB);
    basis_kernel<<<NN / 256, 256>>>();

    // fc0 (writes g_hA) + DFT partials of h0
    combine_kernel<true, false, true><<<g, 256, CMB_SMEM>>>(1, cw, cb, x, t, fc0w, fc0b);

    const size_t SWL = (size_t)64 * 64 * 16;
    // layer 0: read hA -> write hB, gelu, DFT
    reduce_kernel<<<BB, 256>>>();
    modemix_kernel<<<BB, 256>>>(swr + 0 * SWL, swi + 0 * SWL);
    combine_kernel<false, true, true><<<g, 256, CMB_SMEM>>>(0, cw + 0 * 4096, cb + 0 * 64, x, t, fc0w, fc0b);
    // layer 1: hB -> hA
    reduce_kernel<<<BB, 256>>>();
    modemix_kernel<<<BB, 256>>>(swr + 1 * SWL, swi + 1 * SWL);
    combine_kernel<false, true, true><<<g, 256, CMB_SMEM>>>(1, cw + 1 * 4096, cb + 1 * 64, x, t, fc0w, fc0b);
    // layer 2: hA -> hB
    reduce_kernel<<<BB, 256>>>();
    modemix_kernel<<<BB, 256>>>(swr + 2 * SWL, swi + 2 * SWL);
    combine_kernel<false, true, true><<<g, 256, CMB_SMEM>>>(0, cw + 2 * 4096, cb + 2 * 64, x, t, fc0w, fc0b);
    // layer 3: hB -> hA, no gelu, no DFT
    reduce_kernel<<<BB, 256>>>();
    modemix_kernel<<<BB, 256>>>(swr + 3 * SWL, swi + 3 * SWL);
    combine_kernel<false, false, false><<<g, 256, CMB_SMEM>>>(1, cw + 3 * 4096, cb + 3 * 64, x, t, fc0w, fc0b);

    fc12_kernel<<<g, 256, FC_SMEM>>>(w1, b1, w2, b2, out);
}